// round 1
// baseline (speedup 1.0000x reference)
#include <cuda_runtime.h>
#include <cuda_bf16.h>

#define NN 32768      // samples per row
#define BB 4          // batch
#define WW 512        // window
#define FF 127        // frames
#define NFT (BB*FF)   // 508 (b,f) pairs
#define CD 33280      // cot table entries per frame: d in [-511, 32767]

// ---- device scratch (static: no runtime allocation allowed) ----
__device__ unsigned long long d_amax[NFT];
__device__ float d_g[NFT * WW];                 // beta * (-1)^j * hamming * recon
__device__ float d_C[(size_t)NFT * CD];         // cot table per frame (~68 MB)
__device__ float d_Pc[4 * BB * NN];             // partial P per frame-chunk

__device__ __forceinline__ float hamm(int j) {
    // periodic hamming: 0.54 - 0.46*cos(2*pi*j/512)
    return 0.54f - 0.46f * cospif((float)j * (1.0f / 256.0f));
}

// order-preserving pack; ties resolved toward smaller k (matches jnp.argmax)
__device__ __forceinline__ unsigned long long packkey(float v, unsigned k) {
    unsigned u = __float_as_uint(v);
    u = (u & 0x80000000u) ? ~u : (u | 0x80000000u);
    return ((unsigned long long)u << 32) | (0xFFFFFFFFu - k);
}

__global__ void k_init() {
    int i = blockIdx.x * blockDim.x + threadIdx.x;
    if (i < NFT) d_amax[i] = 0ull;
}

// ---- conv1: fm[b,f,k] = sum_j w[j]*t[k-j]; block argmax -> atomicMax ----
__global__ __launch_bounds__(128) void k_conv1(const float* __restrict__ recon,
                                               const float* __restrict__ target) {
    __shared__ __align__(16) float tsh[1024];
    __shared__ __align__(16) float wsh[512];
    __shared__ unsigned long long rsh[128];
    const int tid = threadIdx.x;
    const int k0 = blockIdx.x * 512;
    const int f = blockIdx.y, b = blockIdx.z;
    const float* tb = target + b * NN;
    const float* rb = recon + b * NN + f * 256;

    for (int j = tid; j < 512; j += 128) wsh[j] = hamm(j) * rb[j];
    for (int i = tid; i < 1024; i += 128) {
        int gi = k0 - 512 + i;
        tsh[i] = (gi >= 0) ? tb[gi] : 0.0f;   // zero-pad handles k<j region
    }
    __syncthreads();

    float a0 = 0.f, a1 = 0.f, a2 = 0.f, a3 = 0.f;
    const int base = 4 * tid + 508;
#pragma unroll 4
    for (int j0 = 0; j0 < 512; j0 += 4) {
        float4 wv = *(const float4*)(wsh + j0);
        const float* p = tsh + (base - j0);
        float4 xa = *(const float4*)(p);
        float4 xb = *(const float4*)(p + 4);
        a0 += wv.x * xb.x; a1 += wv.x * xb.y; a2 += wv.x * xb.z; a3 += wv.x * xb.w;
        a0 += wv.y * xa.w; a1 += wv.y * xb.x; a2 += wv.y * xb.y; a3 += wv.y * xb.z;
        a0 += wv.z * xa.z; a1 += wv.z * xa.w; a2 += wv.z * xb.x; a3 += wv.z * xb.y;
        a0 += wv.w * xa.y; a1 += wv.w * xa.z; a2 += wv.w * xa.w; a3 += wv.w * xb.x;
    }

    unsigned kb = (unsigned)(k0 + 4 * tid);
    unsigned long long key = packkey(a0, kb);
    unsigned long long k1 = packkey(a1, kb + 1); if (k1 > key) key = k1;
    unsigned long long k2 = packkey(a2, kb + 2); if (k2 > key) key = k2;
    unsigned long long k3 = packkey(a3, kb + 3); if (k3 > key) key = k3;
    rsh[tid] = key;
    __syncthreads();
    for (int s = 64; s > 0; s >>= 1) {
        if (tid < s) { if (rsh[tid + s] > rsh[tid]) rsh[tid] = rsh[tid + s]; }
        __syncthreads();
    }
    if (tid == 0) atomicMax(&d_amax[b * FF + f], rsh[0]);
}

// ---- per-frame tables: beta, g[j], cot table C[d] ----
__global__ void k_tab(const float* __restrict__ recon) {
    const int bf = blockIdx.x;
    const int b = bf / FF, f = bf % FF;
    const int tid = threadIdx.x;
    unsigned long long key = d_amax[bf];
    unsigned a = 0xFFFFFFFFu - (unsigned)(key & 0xFFFFFFFFull);
    const bool delta = (a == 0u);          // s'=0 -> identity kernel
    const double r = (double)a / 32769.0;  // frac part: s' = a - r
    double beta;
    if (delta) beta = 1.0;
    else beta = ((a & 1u) ? -1.0 : 1.0) * sinpi(r) * (1.0 / 65536.0);

    const float* rb = recon + b * NN + f * 256;
    const float bf32 = (float)beta;
    for (int j = tid; j < WW; j += blockDim.x) {
        float s = (j & 1) ? -1.0f : 1.0f;
        d_g[bf * WW + j] = bf32 * s * hamm(j) * rb[j];
    }

    float* Crow = d_C + (size_t)bf * CD;
    if (delta) {
        for (int i = tid; i < CD; i += blockDim.x) Crow[i] = (i == 511) ? 1.0f : 0.0f;
    } else {
        for (int i = tid; i < CD; i += blockDim.x) {
            int d = i - 511;
            // u = (d - s')/(2n) = ((d-a) + r)/65536, reduced in double, never 0
            double u = ((double)(d - (int)a) + r) * (1.0 / 65536.0);
            float uf = (float)u;
            Crow[i] = __fdividef(cospif(uf), sinpif(uf));
        }
    }
}

// ---- conv2: P[b,m] = (-1)^m * sum_f sum_j g[f,j] * C_f[m-j] ----
__global__ __launch_bounds__(128) void k_conv2() {
    __shared__ __align__(16) float csh[1024];
    __shared__ __align__(16) float gsh[512];
    const int tid = threadIdx.x;
    const int m0 = blockIdx.x * 512;
    const int chunk = blockIdx.y, b = blockIdx.z;
    const int f0 = chunk * 32;
    const int f1 = (f0 + 32 < FF) ? (f0 + 32) : FF;

    float a0 = 0.f, a1 = 0.f, a2 = 0.f, a3 = 0.f;
    const int base = 4 * tid + 508;
    for (int f = f0; f < f1; f++) {
        const int bf = b * FF + f;
        const float* Crow = d_C + (size_t)bf * CD;
        for (int i = tid; i < 1024; i += 128) {
            int col = m0 + i - 1;                 // table index = (m0-512+i) + 511
            csh[i] = (col >= 0) ? Crow[col] : 0.0f;
        }
        for (int j = tid; j < 512; j += 128) gsh[j] = d_g[bf * WW + j];
        __syncthreads();
#pragma unroll 4
        for (int j0 = 0; j0 < 512; j0 += 4) {
            float4 wv = *(const float4*)(gsh + j0);
            const float* p = csh + (base - j0);
            float4 xa = *(const float4*)(p);
            float4 xb = *(const float4*)(p + 4);
            a0 += wv.x * xb.x; a1 += wv.x * xb.y; a2 += wv.x * xb.z; a3 += wv.x * xb.w;
            a0 += wv.y * xa.w; a1 += wv.y * xb.x; a2 += wv.y * xb.y; a3 += wv.y * xb.z;
            a0 += wv.z * xa.z; a1 += wv.z * xa.w; a2 += wv.z * xb.x; a3 += wv.z * xb.y;
            a0 += wv.w * xa.y; a1 += wv.w * xa.z; a2 += wv.w * xa.w; a3 += wv.w * xb.x;
        }
        __syncthreads();
    }
    const int m = m0 + 4 * tid;   // m0+4t even -> sign by c parity
    float* P = d_Pc + ((size_t)(chunk * BB + b)) * NN;
    P[m]     =  a0;
    P[m + 1] = -a1;
    P[m + 2] =  a2;
    P[m + 3] = -a3;
}

// ---- final MSE reduction ----
__global__ void k_loss(const float* __restrict__ target, float* __restrict__ out) {
    __shared__ double red[256];
    const int tid = threadIdx.x;
    double s = 0.0;
    for (int i = tid; i < BB * NN; i += 256) {
        int b = i >> 15, m = i & (NN - 1);
        float p = d_Pc[(0 * BB + b) * NN + m] + d_Pc[(1 * BB + b) * NN + m]
                + d_Pc[(2 * BB + b) * NN + m] + d_Pc[(3 * BB + b) * NN + m];
        double dd = (double)p - (double)target[i];
        s += dd * dd;
    }
    red[tid] = s;
    __syncthreads();
    for (int st = 128; st > 0; st >>= 1) {
        if (tid < st) red[tid] += red[tid + st];
        __syncthreads();
    }
    if (tid == 0) out[0] = (float)(red[0] / (double)(BB * NN));
}

extern "C" void kernel_launch(void* const* d_in, const int* in_sizes, int n_in,
                              void* d_out, int out_size) {
    const float* recon  = (const float*)d_in[0];
    const float* target = (const float*)d_in[1];
    float* out = (float*)d_out;
    (void)in_sizes; (void)n_in; (void)out_size;

    k_init<<<2, 256>>>();
    k_conv1<<<dim3(64, FF, BB), 128>>>(recon, target);
    k_tab<<<NFT, 256>>>(recon);
    k_conv2<<<dim3(64, 4, BB), 128>>>();
    k_loss<<<1, 256>>>(target, out);
}

// round 2
// speedup vs baseline: 1.8277x; 1.8277x over previous
#include <cuda_runtime.h>
#include <cuda_bf16.h>

#define NN 32768
#define BB 4
#define WW 512
#define FF 127
#define NFT (BB*FF)
#define TILE 1024
#define NTILES (NN/TILE)     // 32
#define NCHUNK 8             // frame chunks in conv2
#define FPC 16               // frames per chunk

// ---- device scratch ----
__device__ unsigned long long d_amax[NFT];
__device__ float d_Pc[NCHUNK * BB * NN];
__device__ double d_acc;

__device__ __forceinline__ float hamm(int j) {
    return 0.54f - 0.46f * cospif((float)j * (1.0f / 256.0f));
}

// order-preserving pack; ties -> smaller k wins (matches jnp.argmax)
__device__ __forceinline__ unsigned long long packkey(float v, unsigned k) {
    unsigned u = __float_as_uint(v);
    u = (u & 0x80000000u) ? ~u : (u | 0x80000000u);
    return ((unsigned long long)u << 32) | (0xFFFFFFFFu - k);
}

__global__ void k_init() {
    int i = blockIdx.x * blockDim.x + threadIdx.x;
    if (i < NFT) d_amax[i] = 0ull;
    if (i == NFT) d_acc = 0.0;
}

// Register-sliding-window 512-tap conv: 8 outputs/thread, 8 taps/iter.
// csh[i] = x[tile0 - 512 + i], valid i in [-8, 1535] (8-float front pad).
__device__ __forceinline__ void conv_tile(const float* __restrict__ csh,
                                          const float* __restrict__ wsh,
                                          int tid, float acc[8]) {
    const int p0 = 8 * tid + 512;
    float x[16];   // x[i] = csh[p - 8 + i], p = p0 - j0
    {
        float4 t0 = *(const float4*)(csh + p0 - 8);
        float4 t1 = *(const float4*)(csh + p0 - 4);
        float4 t2 = *(const float4*)(csh + p0);
        float4 t3 = *(const float4*)(csh + p0 + 4);
        x[0]=t0.x; x[1]=t0.y; x[2]=t0.z; x[3]=t0.w;
        x[4]=t1.x; x[5]=t1.y; x[6]=t1.z; x[7]=t1.w;
        x[8]=t2.x; x[9]=t2.y; x[10]=t2.z; x[11]=t2.w;
        x[12]=t3.x; x[13]=t3.y; x[14]=t3.z; x[15]=t3.w;
    }
#pragma unroll 4
    for (int j0 = 0; j0 < 512; j0 += 8) {
        float4 w0 = *(const float4*)(wsh + j0);
        float4 w1 = *(const float4*)(wsh + j0 + 4);
        float wr[8] = {w0.x, w0.y, w0.z, w0.w, w1.x, w1.y, w1.z, w1.w};
#pragma unroll
        for (int c = 0; c < 8; c++)
#pragma unroll
            for (int t = 0; t < 8; t++)
                acc[t] = fmaf(wr[c], x[8 + t - c], acc[t]);
        // slide window down by 8: x'[8..15] = x[0..7], x'[0..7] = new loads
#pragma unroll
        for (int i = 15; i >= 8; i--) x[i] = x[i - 8];
        float4 n0 = *(const float4*)(csh + p0 - j0 - 16);
        float4 n1 = *(const float4*)(csh + p0 - j0 - 12);
        x[0]=n0.x; x[1]=n0.y; x[2]=n0.z; x[3]=n0.w;
        x[4]=n1.x; x[5]=n1.y; x[6]=n1.z; x[7]=n1.w;
    }
}

// ---- conv1: fm[b,f,k] = sum_j w[j]*t[k-j]; block argmax -> atomicMax ----
__global__ __launch_bounds__(128) void k_conv1(const float* __restrict__ recon,
                                               const float* __restrict__ target) {
    __shared__ __align__(16) float csh_raw[8 + 1536];
    __shared__ __align__(16) float wsh[512];
    __shared__ unsigned long long rsh[128];
    float* csh = csh_raw + 8;
    const int tid = threadIdx.x;
    const int tile0 = blockIdx.x * TILE;
    const int f = blockIdx.y, b = blockIdx.z;
    const float* tb = target + b * NN;
    const float* rb = recon + b * NN + f * 256;

    for (int j = tid; j < 512; j += 128) wsh[j] = hamm(j) * rb[j];
    for (int i = tid; i < 1544; i += 128) {
        int gi = tile0 - 520 + i;
        csh_raw[i] = (gi >= 0 && gi < NN) ? tb[gi] : 0.0f;
    }
    __syncthreads();

    float acc[8] = {0.f,0.f,0.f,0.f,0.f,0.f,0.f,0.f};
    conv_tile(csh, wsh, tid, acc);

    unsigned kb = (unsigned)(tile0 + 8 * tid);
    unsigned long long key = packkey(acc[0], kb);
#pragma unroll
    for (int t = 1; t < 8; t++) {
        unsigned long long kt = packkey(acc[t], kb + t);
        if (kt > key) key = kt;
    }
    rsh[tid] = key;
    __syncthreads();
    for (int s = 64; s > 0; s >>= 1) {
        if (tid < s) { if (rsh[tid + s] > rsh[tid]) rsh[tid] = rsh[tid + s]; }
        __syncthreads();
    }
    if (tid == 0) atomicMax(&d_amax[b * FF + f], rsh[0]);
}

// ---- conv2: P[b,m] = (-1)^m * sum_f sum_j g[f,j] * C_f[m-j], C computed inline ----
__global__ __launch_bounds__(128) void k_conv2(const float* __restrict__ recon) {
    __shared__ __align__(16) float csh_raw[8 + 1536];
    __shared__ __align__(16) float wsh[512];
    float* csh = csh_raw + 8;
    const int tid = threadIdx.x;
    const int tile0 = blockIdx.x * TILE;
    const int chunk = blockIdx.y, b = blockIdx.z;
    const int f0 = chunk * FPC;
    const int f1 = (f0 + FPC < FF) ? (f0 + FPC) : FF;

    float acc[8] = {0.f,0.f,0.f,0.f,0.f,0.f,0.f,0.f};

    for (int f = f0; f < f1; f++) {
        const int bf = b * FF + f;
        const unsigned a = 0xFFFFFFFFu - (unsigned)(d_amax[bf] & 0xFFFFFFFFull);
        const bool delta = (a == 0u);
        const float r = (float)a * (1.0f / 32769.0f);
        const float beta = delta ? 1.0f
            : ((a & 1u) ? -1.0f : 1.0f) * sinpif(r) * (1.0f / 65536.0f);
        const float* rb = recon + b * NN + f * 256;

        __syncthreads();   // previous frame's conv done before overwriting tiles
        for (int j = tid; j < 512; j += 128) {
            float s = (j & 1) ? -1.0f : 1.0f;
            wsh[j] = beta * s * hamm(j) * rb[j];
        }
        for (int i = tid; i < 1544; i += 128) {
            int pos = tile0 - 520 + i;     // d = m - j
            float v;
            if (delta) {
                v = (pos == 0) ? 1.0f : 0.0f;
            } else if (pos < -511) {
                v = 0.0f;
            } else {
                float u = ((float)(pos - (int)a) + r) * (1.0f / 65536.0f);
                v = __fdividef(cospif(u), sinpif(u));
            }
            csh_raw[i] = v;
        }
        __syncthreads();

        conv_tile(csh, wsh, tid, acc);
    }

    const int m = tile0 + 8 * tid;         // even -> sign by t parity
    float* P = d_Pc + ((size_t)(chunk * BB + b)) * NN + m;
#pragma unroll
    for (int t = 0; t < 8; t++) P[t] = (t & 1) ? -acc[t] : acc[t];
}

// ---- parallel MSE reduction ----
__global__ void k_loss(const float* __restrict__ target) {
    __shared__ double red[256];
    const int tid = threadIdx.x;
    double s = 0.0;
    for (int i = blockIdx.x * 256 + tid; i < BB * NN; i += gridDim.x * 256) {
        int b = i >> 15, m = i & (NN - 1);
        float p = 0.f;
#pragma unroll
        for (int c = 0; c < NCHUNK; c++)
            p += d_Pc[((size_t)(c * BB + b)) * NN + m];
        double dd = (double)p - (double)target[i];
        s += dd * dd;
    }
    red[tid] = s;
    __syncthreads();
    for (int st = 128; st > 0; st >>= 1) {
        if (tid < st) red[tid] += red[tid + st];
        __syncthreads();
    }
    if (tid == 0) atomicAdd(&d_acc, red[0]);
}

__global__ void k_final(float* __restrict__ out) {
    out[0] = (float)(d_acc / (double)(BB * NN));
}

extern "C" void kernel_launch(void* const* d_in, const int* in_sizes, int n_in,
                              void* d_out, int out_size) {
    const float* recon  = (const float*)d_in[0];
    const float* target = (const float*)d_in[1];
    float* out = (float*)d_out;
    (void)in_sizes; (void)n_in; (void)out_size;

    k_init<<<2, 256>>>();
    k_conv1<<<dim3(NTILES, FF, BB), 128>>>(recon, target);
    k_conv2<<<dim3(NTILES, NCHUNK, BB), 128>>>(recon);
    k_loss<<<128, 256>>>(target);
    k_final<<<1, 1>>>(out);
}

// round 3
// speedup vs baseline: 2.6913x; 1.4725x over previous
#include <cuda_runtime.h>
#include <cuda_bf16.h>

#define NN 32768
#define BB 4
#define WW 512
#define FF 127
#define NFT (BB*FF)
#define TILE 4096
#define NEAR_LO 3584
#define NEAR_SPAN 8192

// ---- device scratch ----
__device__ unsigned long long d_amax[NFT];
__device__ float d_P[BB * NN];
__device__ float d_ftab[NFT * 8];   // per frame: {a_bits, r, M0, M1, M2, M3, -, -}
__device__ double d_acc;

__device__ __forceinline__ float hamm(int j) {
    return 0.54f - 0.46f * cospif((float)j * (1.0f / 256.0f));
}

// order-preserving pack; ties -> smaller k wins (matches jnp.argmax)
__device__ __forceinline__ unsigned long long packkey(float v, unsigned k) {
    unsigned u = __float_as_uint(v);
    u = (u & 0x80000000u) ? ~u : (u | 0x80000000u);
    return ((unsigned long long)u << 32) | (0xFFFFFFFFu - k);
}

__global__ void k_init() {
    int i = blockIdx.x * blockDim.x + threadIdx.x;
    if (i < NFT) d_amax[i] = 0ull;
    if (i == NFT) d_acc = 0.0;
}

// Register-sliding-window 512-tap conv: 16 outputs/thread, 8 taps/iter.
// csh[i] = x[tile0 - 512 + i]; csh valid for i in [-16, 4607].
__device__ __forceinline__ void conv16(const float* __restrict__ csh,
                                       const float* __restrict__ wsh,
                                       int tid, float* __restrict__ acc) {
    float X[24];   // X[i] = csh[16*tid + 504 - j0 + i]
    const float* base = csh + 16 * tid + 504;
#pragma unroll
    for (int i = 0; i < 6; i++) {
        float4 v = *(const float4*)(base + 4 * i);
        X[4*i+0]=v.x; X[4*i+1]=v.y; X[4*i+2]=v.z; X[4*i+3]=v.w;
    }
#pragma unroll 4
    for (int j0 = 0; j0 < 512; j0 += 8) {
        float4 w0 = *(const float4*)(wsh + j0);
        float4 w1 = *(const float4*)(wsh + j0 + 4);
        float wr[8] = {w0.x,w0.y,w0.z,w0.w,w1.x,w1.y,w1.z,w1.w};
#pragma unroll
        for (int c = 0; c < 8; c++)
#pragma unroll
            for (int t = 0; t < 16; t++)
                acc[t] = fmaf(wr[c], X[8 + t - c], acc[t]);
        // slide window by 8: new X[i] = old X[i-8] for i>=8; X[0..7] fresh
#pragma unroll
        for (int i = 23; i >= 8; i--) X[i] = X[i - 8];
        float4 n0 = *(const float4*)(base - j0 - 8);
        float4 n1 = *(const float4*)(base - j0 - 4);
        X[0]=n0.x; X[1]=n0.y; X[2]=n0.z; X[3]=n0.w;
        X[4]=n1.x; X[5]=n1.y; X[6]=n1.z; X[7]=n1.w;
    }
}

// ---- conv1: fm[b,f,k] = sum_j w[j]*t[k-j]; block argmax -> atomicMax ----
__global__ __launch_bounds__(256, 2) void k_conv1(const float* __restrict__ recon,
                                                  const float* __restrict__ target) {
    __shared__ __align__(16) float raw[4640];
    __shared__ __align__(16) float wsh[512];
    __shared__ unsigned long long rsh[256];
    float* csh = raw + 16;
    const int tid = threadIdx.x;
    const int tile0 = blockIdx.x * TILE;
    const int f = blockIdx.y, b = blockIdx.z;
    const float* tb = target + b * NN;
    const float* rb = recon + b * NN + f * 256;

    for (int j = tid; j < 512; j += 256) wsh[j] = hamm(j) * rb[j];
    for (int i = tid; i < 4624; i += 256) {
        int gi = tile0 - 528 + i;
        raw[i] = (gi >= 0 && gi < NN) ? tb[gi] : 0.0f;
    }
    __syncthreads();

    float acc[16];
#pragma unroll
    for (int t = 0; t < 16; t++) acc[t] = 0.0f;
    conv16(csh, wsh, tid, acc);

    unsigned kb = (unsigned)(tile0 + 16 * tid);
    unsigned long long key = packkey(acc[0], kb);
#pragma unroll
    for (int t = 1; t < 16; t++) {
        unsigned long long kt = packkey(acc[t], kb + t);
        if (kt > key) key = kt;
    }
    rsh[tid] = key;
    __syncthreads();
    for (int s = 128; s > 0; s >>= 1) {
        if (tid < s) { if (rsh[tid + s] > rsh[tid]) rsh[tid] = rsh[tid + s]; }
        __syncthreads();
    }
    if (tid == 0) atomicMax(&d_amax[b * FF + f], rsh[0]);
}

// ---- per-frame params + moments for the far-field expansion ----
__global__ void k_prep(const float* __restrict__ recon) {
    __shared__ float4 red[128];
    const int bf = blockIdx.x;
    const int b = bf / FF, f = bf % FF;
    const int tid = threadIdx.x;
    const unsigned a = 0xFFFFFFFFu - (unsigned)(d_amax[bf] & 0xFFFFFFFFull);
    const bool delta = (a == 0u);
    const float r = (float)a * (1.0f / 32769.0f);
    const float beta = delta ? 1.0f
        : ((a & 1u) ? -1.0f : 1.0f) * sinpif(r) * (1.0f / 65536.0f);
    const float* rb = recon + b * NN + f * 256;

    float m0 = 0.f, m1 = 0.f, m2 = 0.f, m3 = 0.f;
#pragma unroll
    for (int q = 0; q < 4; q++) {
        int j = tid * 4 + q;
        float s = (j & 1) ? -1.0f : 1.0f;
        float g = beta * s * hamm(j) * rb[j];
        float tau = (255.5f - (float)j) * (1.0f / 256.0f);
        float t2 = tau * tau;
        m0 += g; m1 += g * tau; m2 += g * t2; m3 += g * t2 * tau;
    }
    red[tid] = make_float4(m0, m1, m2, m3);
    __syncthreads();
    for (int s = 64; s > 0; s >>= 1) {
        if (tid < s) {
            float4 x = red[tid], y = red[tid + s];
            red[tid] = make_float4(x.x+y.x, x.y+y.y, x.z+y.z, x.w+y.w);
        }
        __syncthreads();
    }
    if (tid == 0) {
        float* e = d_ftab + bf * 8;
        float4 m = red[0];
        e[0] = __int_as_float((int)a);
        e[1] = r;
        e[2] = m.x; e[3] = m.y; e[4] = m.z; e[5] = m.w;
    }
}

// ---- far-field: cubic cot-Taylor x moments; writes d_P (full, non-atomic) ----
__global__ __launch_bounds__(256) void k_far() {
    __shared__ float ft[FF * 8];
    const int tid = threadIdx.x;
    const int b = blockIdx.y;
    for (int i = tid; i < FF * 8; i += 256) ft[i] = d_ftab[b * FF * 8 + i];
    __syncthreads();

    const int m0i = blockIdx.x * 1024 + tid * 4;
    float F[4] = {0.f, 0.f, 0.f, 0.f};
    const float G = 0.01227184630f;   // pi/256

    for (int f = 0; f < FF; f++) {
        const float* e = ft + f * 8;
        int a = __float_as_int(e[0]);
        if (a == 0) continue;                      // delta frame: fully in near band
        float r = e[1], M0 = e[2], M1 = e[3], M2 = e[4], M3 = e[5];
        float dbase = (float)(m0i - a) + (r - 255.5f);
        int rel = m0i - (a - NEAR_LO);
#pragma unroll
        for (int k = 0; k < 4; k++) {
            if ((unsigned)(rel + k) < (unsigned)NEAR_SPAN) continue;  // near band: exact kernel
            float u = (dbase + (float)k) * (1.0f / 65536.0f);
            float c0 = __fdividef(cospif(u), sinpif(u));
            float c2 = c0 * c0;
            float q = c2 + 1.0f;
            float t = fmaf(G, fmaf(G, (c2 + 0.33333333f) * M3, -c0 * M2), M1);
            F[k] = fmaf(c0, M0, fmaf(-G * q, t, F[k]));
        }
    }
    // P = (-1)^m * F ; m0i multiple of 4 -> signs + - + -
    float4 outv = make_float4(F[0], -F[1], F[2], -F[3]);
    *(float4*)(d_P + b * NN + m0i) = outv;
}

// ---- near-field: exact 512-tap conv on the 8192-wide band around the pole ----
__global__ __launch_bounds__(256, 2) void k_near(const float* __restrict__ recon) {
    __shared__ __align__(16) float raw[4640];
    __shared__ __align__(16) float wsh[512];
    float* csh = raw + 16;
    const int tid = threadIdx.x;
    const int f = blockIdx.y, b = blockIdx.z;
    const int bf = b * FF + f;
    const unsigned a = 0xFFFFFFFFu - (unsigned)(d_amax[bf] & 0xFFFFFFFFull);
    const int tile0 = (int)a - NEAR_LO + blockIdx.x * TILE;
    if (tile0 >= NN) return;
    const bool delta = (a == 0u);
    const float r = (float)a * (1.0f / 32769.0f);
    const float beta = delta ? 1.0f
        : ((a & 1u) ? -1.0f : 1.0f) * sinpif(r) * (1.0f / 65536.0f);
    const float* rb = recon + b * NN + f * 256;

    for (int j = tid; j < 512; j += 256) {
        float s = (j & 1) ? -1.0f : 1.0f;
        wsh[j] = beta * s * hamm(j) * rb[j];
    }
    for (int i = tid; i < 4624; i += 256) {
        int d = tile0 - 528 + i;
        float v;
        if (delta) {
            v = (d == 0) ? 1.0f : 0.0f;
        } else if (d < -511) {
            v = 0.0f;
        } else {
            float u = ((float)(d - (int)a) + r) * (1.0f / 65536.0f);
            v = __fdividef(cospif(u), sinpif(u));
        }
        raw[i] = v;
    }
    __syncthreads();

    float acc[16];
#pragma unroll
    for (int t = 0; t < 16; t++) acc[t] = 0.0f;
    conv16(csh, wsh, tid, acc);

    const int mb = tile0 + 16 * tid;
    float* Pb = d_P + b * NN;
#pragma unroll
    for (int t = 0; t < 16; t++) {
        int m = mb + t;
        if ((unsigned)m < (unsigned)NN) {
            float v = (m & 1) ? -acc[t] : acc[t];
            atomicAdd(Pb + m, v);
        }
    }
}

// ---- parallel MSE reduction ----
__global__ void k_loss(const float* __restrict__ target) {
    __shared__ double red[256];
    const int tid = threadIdx.x;
    double s = 0.0;
    for (int i = blockIdx.x * 256 + tid; i < BB * NN; i += gridDim.x * 256) {
        double dd = (double)d_P[i] - (double)target[i];
        s += dd * dd;
    }
    red[tid] = s;
    __syncthreads();
    for (int st = 128; st > 0; st >>= 1) {
        if (tid < st) red[tid] += red[tid + st];
        __syncthreads();
    }
    if (tid == 0) atomicAdd(&d_acc, red[0]);
}

__global__ void k_final(float* __restrict__ out) {
    out[0] = (float)(d_acc / (double)(BB * NN));
}

extern "C" void kernel_launch(void* const* d_in, const int* in_sizes, int n_in,
                              void* d_out, int out_size) {
    const float* recon  = (const float*)d_in[0];
    const float* target = (const float*)d_in[1];
    float* out = (float*)d_out;
    (void)in_sizes; (void)n_in; (void)out_size;

    k_init<<<2, 256>>>();
    k_conv1<<<dim3(NN / TILE, FF, BB), 256>>>(recon, target);
    k_prep<<<NFT, 128>>>(recon);
    k_far<<<dim3(NN / 1024, BB), 256>>>();
    k_near<<<dim3(2, FF, BB), 256>>>(recon);
    k_loss<<<128, 256>>>(target);
    k_final<<<1, 1>>>(out);
}